// round 3
// baseline (speedup 1.0000x reference)
#include <cuda_runtime.h>

// SKA: out[b, g*32+c, h, w] = sum_{di,dj} x[b, g*32+c, h+di-2, w+dj-2] * w[b, g, di*5+dj, h, w]
// x [8,256,64,64] f32, w [8,8,25,64,64] f32, out [8,256,64,64] f32.
//
// Thread = 4 output rows (h0..h0+3) x 4 pixels x 2 channels.
// Row-sliding: x rows h0-2..h0+5 loaded once each, each feeds up to 4 output rows.
// Warp = 16 pixel-groups x 2 channel-pairs -> w LDG dedups across half-warps.

#define B_  8
#define C_  256
#define H_  64
#define W_  64
#define G_  8
#define CG_ 32
#define NC_ 2   // channels per thread
#define RH_ 4   // output rows per thread

__global__ __launch_bounds__(256, 3)
void SKA_60387240182286_kernel(const float* __restrict__ x,
                               const float* __restrict__ wgt,
                               float* __restrict__ out)
{
    const int tid  = threadIdx.x;
    const int wq   = tid & 15;           // 0..15: 4-wide pixel group along W
    const int cpi  = tid >> 4;           // 0..15: channel-pair index (covers all 32 ch)

    const int bg = blockIdx.x;           // 0..63 = b*8 + g
    const int h0 = blockIdx.y * RH_;     // 0,4,...,60
    const int b  = bg >> 3;
    const int g  = bg & 7;
    const int w0 = wq * 4;
    const int c0 = g * CG_ + cpi * NC_;

    const float* xbase = x + ((size_t)(b * C_ + c0)) * (H_ * W_);
    // w base for k=0, row h0, col w0
    const float* wbase = wgt + (((size_t)bg * 25) * H_ + h0) * W_ + w0;

    float acc[RH_][NC_][4];
#pragma unroll
    for (int r = 0; r < RH_; ++r)
#pragma unroll
        for (int c = 0; c < NC_; ++c) {
            acc[r][c][0] = 0.f; acc[r][c][1] = 0.f;
            acc[r][c][2] = 0.f; acc[r][c][3] = 0.f;
        }

    const float2 z2 = make_float2(0.f, 0.f);
    const float4 z4 = make_float4(0.f, 0.f, 0.f, 0.f);
    const bool left_edge  = (wq == 0);
    const bool right_edge = (wq == 15);

#pragma unroll
    for (int hi = 0; hi < RH_ + 4; ++hi) {      // hy = h0 - 2 + hi
        const int hy = h0 - 2 + hi;
        const bool rv = (hy >= 0) && (hy < H_); // only non-trivial at grid edges

        // x window for this row: 8 floats covering columns [w0-2, w0+5], per channel
        float xv[NC_][8];
#pragma unroll
        for (int c = 0; c < NC_; ++c) {
            const float* row = xbase + ((size_t)c * H_ + hy) * W_;
            float2 a = (rv && !left_edge)  ? *(const float2*)(row + w0 - 2) : z2;
            float4 m = rv                  ? *(const float4*)(row + w0)     : z4;
            float2 r = (rv && !right_edge) ? *(const float2*)(row + w0 + 4) : z2;
            xv[c][0] = a.x; xv[c][1] = a.y;
            xv[c][2] = m.x; xv[c][3] = m.y; xv[c][4] = m.z; xv[c][5] = m.w;
            xv[c][6] = r.x; xv[c][7] = r.y;
        }

        // This x row feeds output rows rr = hi - di for di in [0,4], rr in [0,RH)
#pragma unroll
        for (int di = 0; di < 5; ++di) {
            const int rr = hi - di;
            if (rr < 0 || rr >= RH_) continue;  // compile-time prune
#pragma unroll
            for (int dj = 0; dj < 5; ++dj) {
                const int k = di * 5 + dj;
                const float4 wv =
                    *(const float4*)(wbase + ((size_t)k * H_ + rr) * W_);
#pragma unroll
                for (int c = 0; c < NC_; ++c) {
                    acc[rr][c][0] = fmaf(xv[c][dj + 0], wv.x, acc[rr][c][0]);
                    acc[rr][c][1] = fmaf(xv[c][dj + 1], wv.y, acc[rr][c][1]);
                    acc[rr][c][2] = fmaf(xv[c][dj + 2], wv.z, acc[rr][c][2]);
                    acc[rr][c][3] = fmaf(xv[c][dj + 3], wv.w, acc[rr][c][3]);
                }
            }
        }
    }

    float* obase = out + (((size_t)(b * C_ + c0)) * H_ + h0) * W_ + w0;
#pragma unroll
    for (int r = 0; r < RH_; ++r)
#pragma unroll
        for (int c = 0; c < NC_; ++c) {
            *(float4*)(obase + ((size_t)c * H_ + r) * W_) =
                make_float4(acc[r][c][0], acc[r][c][1], acc[r][c][2], acc[r][c][3]);
        }
}

extern "C" void kernel_launch(void* const* d_in, const int* in_sizes, int n_in,
                              void* d_out, int out_size)
{
    const float* x   = (const float*)d_in[0];
    const float* wgt = (const float*)d_in[1];
    float* out = (float*)d_out;

    dim3 grid(B_ * G_, H_ / RH_);   // (64, 16) = 1024 blocks
    SKA_60387240182286_kernel<<<grid, 256>>>(x, wgt, out);
}

// round 4
// speedup vs baseline: 1.2175x; 1.2175x over previous
#include <cuda_runtime.h>

// SKA: out[b, g*32+c, h, w] = sum_{di,dj} x[b, g*32+c, h+di-2, w+dj-2] * w[b, g, di*5+dj, h, w]
// x [8,256,64,64] f32, w [8,8,25,64,64] f32, out [8,256,64,64] f32.
//
// Block = one (b,g) x 2 output rows x all 32 channels x 64 pixels.
// w tile [25][2][64] staged in smem; lane layout (8 wq x 4 cpi) makes each
// w LDS.128 a single conflict-free 128B broadcast wavefront.
// Thread = 2 rows x 4 px x 2 channels = 16 outputs.

#define B_  8
#define C_  256
#define H_  64
#define W_  64
#define G_  8
#define CG_ 32
#define NC_ 2
#define RH_ 2

__global__ __launch_bounds__(256, 4)
void SKA_60387240182286_kernel(const float* __restrict__ x,
                               const float* __restrict__ wgt,
                               float* __restrict__ out)
{
    __shared__ float ws[25 * RH_ * W_];   // [k][rr][w]  = 12.8 KB

    const int tid    = threadIdx.x;
    const int lane   = tid & 31;
    const int warp   = tid >> 5;          // 0..7
    const int wq_lo  = lane & 7;
    const int cpi_lo = lane >> 3;         // 0..3
    const int wq_hi  = warp & 1;
    const int cpi_hi = warp >> 1;         // 0..3
    const int wq  = wq_lo + 8 * wq_hi;    // 0..15
    const int cpi = cpi_lo + 4 * cpi_hi;  // 0..15

    const int bg = blockIdx.x;            // b*8 + g
    const int h0 = blockIdx.y * RH_;      // even
    const int b  = bg >> 3;
    const int g  = bg & 7;
    const int w0 = wq * 4;
    const int c0 = g * CG_ + cpi * NC_;

    // ---- stage w tile: rows h0, h0+1 for all 25 taps (each tap: 128 contiguous floats)
    {
        const float* wsrc = wgt + (((size_t)bg * 25) * H_ + h0) * W_;
        float4* wsv = (float4*)ws;
#pragma unroll
        for (int i = tid; i < 800; i += 256) {    // 800 float4 = 3200 floats
            const int k = i >> 5;                  // tap
            const int r = i & 31;                  // float4 within 128-float chunk
            wsv[i] = *(const float4*)(wsrc + (size_t)k * (H_ * W_) + r * 4);
        }
    }
    __syncthreads();

    const float* xbase = x + ((size_t)(b * C_ + c0)) * (H_ * W_);

    float acc[RH_][NC_][4];
#pragma unroll
    for (int r = 0; r < RH_; ++r)
#pragma unroll
        for (int c = 0; c < NC_; ++c) {
            acc[r][c][0] = 0.f; acc[r][c][1] = 0.f;
            acc[r][c][2] = 0.f; acc[r][c][3] = 0.f;
        }

    const float2 z2 = make_float2(0.f, 0.f);
    const float4 z4 = make_float4(0.f, 0.f, 0.f, 0.f);
    const bool left_edge  = (wq == 0);
    const bool right_edge = (wq == 15);

#pragma unroll
    for (int hi = 0; hi < RH_ + 4; ++hi) {        // x row hy = h0 - 2 + hi
        const int hy = h0 - 2 + hi;
        const bool rv = (hy >= 0) && (hy < H_);

        // x window: 8 floats covering cols [w0-2, w0+5], per channel
        float xv[NC_][8];
#pragma unroll
        for (int c = 0; c < NC_; ++c) {
            const float* row = xbase + ((size_t)c * H_ + hy) * W_;
            float2 a = (rv && !left_edge)  ? *(const float2*)(row + w0 - 2) : z2;
            float4 m = rv                  ? *(const float4*)(row + w0)     : z4;
            float2 r = (rv && !right_edge) ? *(const float2*)(row + w0 + 4) : z2;
            xv[c][0] = a.x; xv[c][1] = a.y;
            xv[c][2] = m.x; xv[c][3] = m.y; xv[c][4] = m.z; xv[c][5] = m.w;
            xv[c][6] = r.x; xv[c][7] = r.y;
        }

        // x row hy feeds output row rr where di = hi - rr in [0,4]
#pragma unroll
        for (int rr = 0; rr < RH_; ++rr) {
            const int di = hi - rr;
            if (di < 0 || di > 4) continue;       // compile-time prune
#pragma unroll
            for (int dj = 0; dj < 5; ++dj) {
                const int k = di * 5 + dj;
                const float4 wv = *(const float4*)(ws + (k * RH_ + rr) * W_ + w0);
#pragma unroll
                for (int c = 0; c < NC_; ++c) {
                    acc[rr][c][0] = fmaf(xv[c][dj + 0], wv.x, acc[rr][c][0]);
                    acc[rr][c][1] = fmaf(xv[c][dj + 1], wv.y, acc[rr][c][1]);
                    acc[rr][c][2] = fmaf(xv[c][dj + 2], wv.z, acc[rr][c][2]);
                    acc[rr][c][3] = fmaf(xv[c][dj + 3], wv.w, acc[rr][c][3]);
                }
            }
        }
    }

    float* obase = out + (((size_t)(b * C_ + c0)) * H_ + h0) * W_ + w0;
#pragma unroll
    for (int r = 0; r < RH_; ++r)
#pragma unroll
        for (int c = 0; c < NC_; ++c) {
            *(float4*)(obase + ((size_t)c * H_ + r) * W_) =
                make_float4(acc[r][c][0], acc[r][c][1], acc[r][c][2], acc[r][c][3]);
        }
}

extern "C" void kernel_launch(void* const* d_in, const int* in_sizes, int n_in,
                              void* d_out, int out_size)
{
    const float* x   = (const float*)d_in[0];
    const float* wgt = (const float*)d_in[1];
    float* out = (float*)d_out;

    dim3 grid(B_ * G_, H_ / RH_);   // (64, 32) = 2048 blocks
    SKA_60387240182286_kernel<<<grid, 256>>>(x, wgt, out);
}

// round 5
// speedup vs baseline: 1.2726x; 1.0453x over previous
#include <cuda_runtime.h>

// SKA: out[b, g*32+c, h, w] = sum_{di,dj} x[b, g*32+c, h+di-2, w+dj-2] * w[b, g, di*5+dj, h, w]
// x [8,256,64,64] f32, w [8,8,25,64,64] f32, out [8,256,64,64] f32.
//
// R4 structure (block = (b,g) x 2 rows x 32 ch x 64 px; w tile in smem with
// 1-wavefront broadcast LDS.128) + software-pipelined x loads: the 12 LDGs for
// x row hi+1 are issued before the FMAs consuming row hi, hiding L2/DRAM latency.

#define B_  8
#define C_  256
#define H_  64
#define W_  64
#define G_  8
#define CG_ 32
#define NC_ 2
#define RH_ 2

__global__ __launch_bounds__(256, 3)
void SKA_60387240182286_kernel(const float* __restrict__ x,
                               const float* __restrict__ wgt,
                               float* __restrict__ out)
{
    __shared__ float ws[25 * RH_ * W_];   // [k][rr][w] = 12.8 KB

    const int tid    = threadIdx.x;
    const int lane   = tid & 31;
    const int warp   = tid >> 5;          // 0..7
    const int wq_lo  = lane & 7;
    const int cpi_lo = lane >> 3;         // 0..3
    const int wq_hi  = warp & 1;
    const int cpi_hi = warp >> 1;         // 0..3
    const int wq  = wq_lo + 8 * wq_hi;    // 0..15
    const int cpi = cpi_lo + 4 * cpi_hi;  // 0..15

    const int bg = blockIdx.x;            // b*8 + g
    const int h0 = blockIdx.y * RH_;
    const int b  = bg >> 3;
    const int g  = bg & 7;
    const int w0 = wq * 4;
    const int c0 = g * CG_ + cpi * NC_;

    // ---- stage w tile: rows h0..h0+1, all 25 taps
    {
        const float* wsrc = wgt + (((size_t)bg * 25) * H_ + h0) * W_;
        float4* wsv = (float4*)ws;
#pragma unroll
        for (int i = tid; i < 800; i += 256) {
            const int k = i >> 5;
            const int r = i & 31;
            wsv[i] = *(const float4*)(wsrc + (size_t)k * (H_ * W_) + r * 4);
        }
    }
    __syncthreads();

    const float* xbase = x + ((size_t)(b * C_ + c0)) * (H_ * W_);

    float acc[RH_][NC_][4];
#pragma unroll
    for (int r = 0; r < RH_; ++r)
#pragma unroll
        for (int c = 0; c < NC_; ++c) {
            acc[r][c][0] = 0.f; acc[r][c][1] = 0.f;
            acc[r][c][2] = 0.f; acc[r][c][3] = 0.f;
        }

    const float2 z2 = make_float2(0.f, 0.f);
    const float4 z4 = make_float4(0.f, 0.f, 0.f, 0.f);
    const bool left_edge  = (wq == 0);
    const bool right_edge = (wq == 15);

    // Two x-window buffers (software pipeline): [buf][channel][8 floats, cols w0-2..w0+5]
    float xv[2][NC_][8];

    // prologue: load row hi=0 (hy = h0-2) into buf 0
    {
        const int hy = h0 - 2;
        const bool rv = (hy >= 0);
#pragma unroll
        for (int c = 0; c < NC_; ++c) {
            const float* row = xbase + ((size_t)c * H_ + hy) * W_;
            float2 a = (rv && !left_edge)  ? *(const float2*)(row + w0 - 2) : z2;
            float4 m = rv                  ? *(const float4*)(row + w0)     : z4;
            float2 r = (rv && !right_edge) ? *(const float2*)(row + w0 + 4) : z2;
            xv[0][c][0] = a.x; xv[0][c][1] = a.y;
            xv[0][c][2] = m.x; xv[0][c][3] = m.y; xv[0][c][4] = m.z; xv[0][c][5] = m.w;
            xv[0][c][6] = r.x; xv[0][c][7] = r.y;
        }
    }

#pragma unroll
    for (int hi = 0; hi < RH_ + 4; ++hi) {        // x row hy = h0 - 2 + hi
        const int cur = hi & 1;
        const int nxt = cur ^ 1;

        // ---- prefetch row hi+1 into the other buffer
        if (hi < RH_ + 3) {
            const int hyn = h0 - 1 + hi;
            const bool rvn = (hyn >= 0) && (hyn < H_);
#pragma unroll
            for (int c = 0; c < NC_; ++c) {
                const float* row = xbase + ((size_t)c * H_ + hyn) * W_;
                float2 a = (rvn && !left_edge)  ? *(const float2*)(row + w0 - 2) : z2;
                float4 m = rvn                  ? *(const float4*)(row + w0)     : z4;
                float2 r = (rvn && !right_edge) ? *(const float2*)(row + w0 + 4) : z2;
                xv[nxt][c][0] = a.x; xv[nxt][c][1] = a.y;
                xv[nxt][c][2] = m.x; xv[nxt][c][3] = m.y;
                xv[nxt][c][4] = m.z; xv[nxt][c][5] = m.w;
                xv[nxt][c][6] = r.x; xv[nxt][c][7] = r.y;
            }
        }

        // ---- compute with row hi (already resident in xv[cur])
#pragma unroll
        for (int rr = 0; rr < RH_; ++rr) {
            const int di = hi - rr;
            if (di < 0 || di > 4) continue;       // compile-time prune
#pragma unroll
            for (int dj = 0; dj < 5; ++dj) {
                const int k = di * 5 + dj;
                const float4 wv = *(const float4*)(ws + (k * RH_ + rr) * W_ + w0);
#pragma unroll
                for (int c = 0; c < NC_; ++c) {
                    acc[rr][c][0] = fmaf(xv[cur][c][dj + 0], wv.x, acc[rr][c][0]);
                    acc[rr][c][1] = fmaf(xv[cur][c][dj + 1], wv.y, acc[rr][c][1]);
                    acc[rr][c][2] = fmaf(xv[cur][c][dj + 2], wv.z, acc[rr][c][2]);
                    acc[rr][c][3] = fmaf(xv[cur][c][dj + 3], wv.w, acc[rr][c][3]);
                }
            }
        }
    }

    float* obase = out + (((size_t)(b * C_ + c0)) * H_ + h0) * W_ + w0;
#pragma unroll
    for (int r = 0; r < RH_; ++r)
#pragma unroll
        for (int c = 0; c < NC_; ++c) {
            *(float4*)(obase + ((size_t)c * H_ + r) * W_) =
                make_float4(acc[r][c][0], acc[r][c][1], acc[r][c][2], acc[r][c][3]);
        }
}

extern "C" void kernel_launch(void* const* d_in, const int* in_sizes, int n_in,
                              void* d_out, int out_size)
{
    const float* x   = (const float*)d_in[0];
    const float* wgt = (const float*)d_in[1];
    float* out = (float*)d_out;

    dim3 grid(B_ * G_, H_ / RH_);   // (64, 32) = 2048 blocks
    SKA_60387240182286_kernel<<<grid, 256>>>(x, wgt, out);
}